// round 13
// baseline (speedup 1.0000x reference)
#include <cuda_runtime.h>
#include <cuda_bf16.h>
#include <cstdint>

#define NNODE 50000
#define HDIM  128
#define GNUM  64
#define EPSBN 1e-5f

// ---------------- device scratch (no allocs allowed) ----------------
__device__ float g_K [NNODE * HDIM];
__device__ float g_Q [NNODE * HDIM];
__device__ float g_V [NNODE * HDIM];
__device__ float g_H0[NNODE * HDIM];
__device__ float g_H1[NNODE * HDIM];
__device__ float g_pool[GNUM * 2 * HDIM];
__device__ float g_h1m[GNUM * HDIM];
__device__ float g_h2m[GNUM * (HDIM / 2)];
// pre-split frag-ordered weights: [sel 0..7][kt 0..3][2560 u32]
__device__ uint32_t g_BFHg[8 * 4 * 2560];
__device__ uint32_t g_BFLg[8 * 4 * 2560];

// ---------------- bf16 split helpers ----------------
__device__ __forceinline__ void split2(float x, float y, uint32_t& hi, uint32_t& lo) {
    __nv_bfloat162 h = __floats2bfloat162_rn(x, y);
    float hx = __bfloat162float(h.x);
    float hy = __bfloat162float(h.y);
    __nv_bfloat162 l = __floats2bfloat162_rn(x - hx, y - hy);
    hi = *(uint32_t*)&h;
    lo = *(uint32_t*)&l;
}

__device__ __forceinline__ void mma_bf16(float c[4], const uint32_t a[4], const uint32_t b[2]) {
    asm volatile(
        "mma.sync.aligned.m16n8k16.row.col.f32.bf16.bf16.f32 "
        "{%0,%1,%2,%3}, {%4,%5,%6,%7}, {%8,%9}, {%0,%1,%2,%3};"
        : "+f"(c[0]), "+f"(c[1]), "+f"(c[2]), "+f"(c[3])
        : "r"(a[0]), "r"(a[1]), "r"(a[2]), "r"(a[3]), "r"(b[0]), "r"(b[1]));
}

// lane permutation to de-alias writer banks; readers apply identically
__device__ __forceinline__ int PERM(int l) { return l ^ ((l & 8) >> 3); }

__device__ __forceinline__ void cp_async16(uint32_t smem_addr, const void* gptr) {
    asm volatile("cp.async.ca.shared.global [%0], [%1], 16;"
                 :: "r"(smem_addr), "l"(gptr));
}

// ---------------- prep: split 8 weight matrices into frag-ordered gmem -----
__global__ void split_wfrag_kernel(
    const float* __restrict__ w0, const float* __restrict__ w1,
    const float* __restrict__ w2, const float* __restrict__ w3,
    const float* __restrict__ w4, const float* __restrict__ w5,
    const float* __restrict__ w6, const float* __restrict__ w7,
    uint32_t* __restrict__ BH, uint32_t* __restrict__ BL)
{
    const int sel   = blockIdx.x >> 3;
    const int slice = blockIdx.x & 7;        // 16-row slice
    const float* w = (sel == 0) ? w0 : (sel == 1) ? w1 : (sel == 2) ? w2 : (sel == 3) ? w3
                   : (sel == 4) ? w4 : (sel == 5) ? w5 : (sel == 6) ? w6 : w7;
    const int tid = threadIdx.x;
#pragma unroll
    for (int it = 0; it < 2; it++) {
        const int idx = tid + it * 256;      // 0..511
        const int n   = slice * 16 + (idx >> 5);   // row 0..127
        const int c4g = (idx & 31) * 4;      // global k offset 0..124
        const float4 b = *(const float4*)(w + (long)n * HDIM + c4g);
        uint32_t h0, l0, h1, l1;
        split2(b.x, b.y, h0, l0);
        split2(b.z, b.w, h1, l1);
        const int kt  = c4g >> 5;
        const int c4l = c4g & 31;
        const int bwn = n >> 6;
        const int c64 = n & 63;
        const int nt  = c64 >> 3;
        const int btp = c64 & 7;
#pragma unroll
        for (int u = 0; u < 2; u++) {
            const int kp  = (c4l >> 1) + u;
            const int ks  = kp >> 3;
            const int kp8 = kp & 7;
            const int wl  = PERM(btp * 4 + (kp8 & 3));
            const int reg = kp8 >> 2;
            const long bi = (long)(sel * 4 + kt) * 2560
                          + ((bwn * 2 + ks) * 32 + wl) * 20 + nt * 2 + reg;
            BH[bi] = (u == 0) ? h0 : h1;
            BL[bi] = (u == 0) ? l0 : l1;
        }
    }
}

// ---------------- bf16x3 GEMM: A split once, 2 sels per block, B pipelined --
// grid = (ceil(N/128), 2), 256 threads. Each block computes 2 outputs
// (sels blockIdx.y*2, +1). A frag smem for all 4 k-tiles built once;
// B k-tiles stream via cp.async double buffer.
// dynamic smem (u32): [AFH 8192][AFL 8192][stg0: H 2560|L 2560][stg1: H|L]
#define SM_AFL  8192
#define SM_BST  16384
#define SM_STSZ 5120
template <bool RELU_IN>
__global__ __launch_bounds__(256) void gemm_bf16x3_kernel(
    const float* __restrict__ X,
    const uint32_t* __restrict__ BFHg, const uint32_t* __restrict__ BFLg,
    const float* __restrict__ bk, const float* __restrict__ bq,
    const float* __restrict__ bv, const float* __restrict__ bs,
    float* __restrict__ oK, float* __restrict__ oQ,
    float* __restrict__ oV, float* __restrict__ oS, int N, int wbase)
{
    extern __shared__ uint32_t smem[];
    uint32_t* AFH = smem;
    uint32_t* AFL = smem + SM_AFL;
    const int m0 = blockIdx.x * 128;

    const int tid  = threadIdx.x;
    const int wid  = tid >> 5;
    const int lane = tid & 31;
    const int wm   = wid & 3;        // 0..3 -> 32-row slab
    const int wn   = wid >> 2;       // 0..1 -> 64-col slab
    const int tig  = lane & 3;
    const int tp   = lane >> 2;
    const int pl   = PERM(lane);

    // B stage loader: step i in 0..7 -> sel2 = i>>2, kt = i&3
    auto load_B = [&](int i) {
        const int sel = blockIdx.y * 2 + (i >> 2);
        const int kt  = i & 3;
        const uint32_t* gBH = BFHg + (long)(wbase + sel) * 4 * 2560 + kt * 2560;
        const uint32_t* gBL = BFLg + (long)(wbase + sel) * 4 * 2560 + kt * 2560;
        uint32_t* st = smem + SM_BST + (i & 1) * SM_STSZ;
#pragma unroll
        for (int j = 0; j < 5; j++) {
            const int c = tid + j * 256;     // 0..1279 (16B chunks)
            if (c < 640) {
                cp_async16((uint32_t)__cvta_generic_to_shared(st + c * 4), gBH + c * 4);
            } else {
                const int c2 = c - 640;
                cp_async16((uint32_t)__cvta_generic_to_shared(st + 2560 + c2 * 4), gBL + c2 * 4);
            }
        }
        asm volatile("cp.async.commit_group;" ::: "memory");
    };

    load_B(0);
    load_B(1);

    // ---- load + split A, ALL 4 k-tiles, once ----
#pragma unroll
    for (int it = 0; it < 16; it++) {
        const int idx = tid + it * 256;       // 0..4095
        const int row = idx >> 5;             // 0..127
        const int c4g = (idx & 31) * 4;       // 0..124
        const int gm  = m0 + row;
        float4 a = make_float4(0.f, 0.f, 0.f, 0.f);
        if (gm < N) a = *(const float4*)(X + (long)gm * HDIM + c4g);
        if (RELU_IN) {
            a.x = fmaxf(a.x, 0.f); a.y = fmaxf(a.y, 0.f);
            a.z = fmaxf(a.z, 0.f); a.w = fmaxf(a.w, 0.f);
        }
        uint32_t h0, l0, h1, l1;
        split2(a.x, a.y, h0, l0);
        split2(a.z, a.w, h1, l1);
        const int kt  = c4g >> 5;
        const int c4l = c4g & 31;
        const int awm = row >> 5;
        const int amt = (row >> 4) & 1;
        const int r16 = row & 15;
        const int atp = r16 & 7;
        const int jrow = r16 >> 3;
#pragma unroll
        for (int u = 0; u < 2; u++) {
            const int kp  = (c4l >> 1) + u;
            const int ks  = kp >> 3;
            const int kp8 = kp & 7;
            const int wl  = PERM(atp * 4 + (kp8 & 3));
            const int j   = jrow + ((kp8 >> 2) << 1);
            const int ai  = kt * 2048 + (((awm * 2 + amt) * 2 + ks) * 32 + wl) * 4 + j;
            AFH[ai] = (u == 0) ? h0 : h1;
            AFL[ai] = (u == 0) ? l0 : l1;
        }
    }
    __syncthreads();   // A frags visible to all warps

    float c[2][8][4];
#pragma unroll
    for (int mt = 0; mt < 2; mt++)
#pragma unroll
        for (int nt = 0; nt < 8; nt++)
#pragma unroll
            for (int j = 0; j < 4; j++) c[mt][nt][j] = 0.f;

#pragma unroll
    for (int i = 0; i < 8; i++) {
        const int kt = i & 3;
        if (i == 7) asm volatile("cp.async.wait_group 0;" ::: "memory");
        else        asm volatile("cp.async.wait_group 1;" ::: "memory");
        __syncthreads();   // stage (i&1) ready for all warps

        const uint32_t* BH = smem + SM_BST + (i & 1) * SM_STSZ;
        const uint32_t* BL = BH + 2560;

#pragma unroll
        for (int ks = 0; ks < 2; ks++) {
            uint32_t ah[2][4], al[2][4];
#pragma unroll
            for (int mt = 0; mt < 2; mt++) {
                const uint32_t base = kt * 2048 + (((wm * 2 + mt) * 2 + ks) * 32 + pl) * 4;
                uint4 th = *(const uint4*)&AFH[base];
                uint4 tl = *(const uint4*)&AFL[base];
                ah[mt][0] = th.x; ah[mt][1] = th.y; ah[mt][2] = th.z; ah[mt][3] = th.w;
                al[mt][0] = tl.x; al[mt][1] = tl.y; al[mt][2] = tl.z; al[mt][3] = tl.w;
            }
            uint32_t bhw[16], blw[16];
            {
                const uint32_t base = ((wn * 2 + ks) * 32 + pl) * 20;
#pragma unroll
                for (int q = 0; q < 4; q++) {
                    uint4 th = *(const uint4*)&BH[base + q * 4];
                    bhw[q * 4 + 0] = th.x; bhw[q * 4 + 1] = th.y;
                    bhw[q * 4 + 2] = th.z; bhw[q * 4 + 3] = th.w;
                    uint4 tl = *(const uint4*)&BL[base + q * 4];
                    blw[q * 4 + 0] = tl.x; blw[q * 4 + 1] = tl.y;
                    blw[q * 4 + 2] = tl.z; blw[q * 4 + 3] = tl.w;
                }
            }
#pragma unroll
            for (int mt = 0; mt < 2; mt++)
#pragma unroll
                for (int nt = 0; nt < 8; nt++) {
                    const uint32_t bh2[2] = {bhw[2 * nt], bhw[2 * nt + 1]};
                    const uint32_t bl2[2] = {blw[2 * nt], blw[2 * nt + 1]};
                    mma_bf16(c[mt][nt], ah[mt], bl2);   // cross terms
                    mma_bf16(c[mt][nt], al[mt], bh2);
                    mma_bf16(c[mt][nt], ah[mt], bh2);   // main term
                }
        }
        __syncthreads();   // all warps done with stage before overwrite
        if (i + 2 < 8) load_B(i + 2);

        if (kt == 3) {   // epilogue for this sel, then reset accumulators
            const int sel = blockIdx.y * 2 + (i >> 2);
            const float* bias = (sel == 0) ? bk : (sel == 1) ? bq : (sel == 2) ? bv : bs;
            float*       out  = (sel == 0) ? oK : (sel == 1) ? oQ : (sel == 2) ? oV : oS;
#pragma unroll
            for (int nt = 0; nt < 8; nt++) {
                const int col = wn * 64 + nt * 8 + 2 * tig;
                const float b0 = bias[col];
                const float b1 = bias[col + 1];
#pragma unroll
                for (int mt = 0; mt < 2; mt++) {
                    const int r0 = m0 + wm * 32 + mt * 16 + tp;
                    const int r1 = r0 + 8;
                    if (r0 < N) {
                        float2 v = make_float2(c[mt][nt][0] + b0, c[mt][nt][1] + b1);
                        *(float2*)(out + (long)r0 * HDIM + col) = v;
                    }
                    if (r1 < N) {
                        float2 v = make_float2(c[mt][nt][2] + b0, c[mt][nt][3] + b1);
                        *(float2*)(out + (long)r1 * HDIM + col) = v;
                    }
                }
            }
#pragma unroll
            for (int mt = 0; mt < 2; mt++)
#pragma unroll
                for (int nt = 0; nt < 8; nt++)
#pragma unroll
                    for (int j = 0; j < 4; j++) c[mt][nt][j] = 0.f;
        }
    }
}

// ---------------- edge kernel: 2 edges per warp, phase-split (R6-proven) ---
__global__ __launch_bounds__(256) void edge_kernel(
    const int* __restrict__ ei, int E,
    const float* __restrict__ K, const float* __restrict__ Q,
    const float* __restrict__ V, float* __restrict__ AGG)
{
    const int w    = (blockIdx.x * blockDim.x + threadIdx.x) >> 5;
    const int lane = threadIdx.x & 31;
    const int e0   = w * 2;
    if (e0 >= E) return;
    const int e1   = (e0 + 1 < E) ? e0 + 1 : e0;

    const int s0 = __ldg(ei + e0);
    const int s1 = __ldg(ei + e1);
    const int d0 = __ldg(ei + E + e0);
    const int d1 = __ldg(ei + E + e1);

    const float4 k0 = *(const float4*)(K + (long)d0 * HDIM + lane * 4);
    const float4 q0 = *(const float4*)(Q + (long)s0 * HDIM + lane * 4);
    const float4 v0 = *(const float4*)(V + (long)s0 * HDIM + lane * 4);
    const float4 k1 = *(const float4*)(K + (long)d1 * HDIM + lane * 4);
    const float4 q1 = *(const float4*)(Q + (long)s1 * HDIM + lane * 4);
    const float4 v1 = *(const float4*)(V + (long)s1 * HDIM + lane * 4);

    {
        const float g0 = 1.f / (1.f + __expf(-(k0.x + q0.x)));
        const float g1 = 1.f / (1.f + __expf(-(k0.y + q0.y)));
        const float g2 = 1.f / (1.f + __expf(-(k0.z + q0.z)));
        const float g3 = 1.f / (1.f + __expf(-(k0.w + q0.w)));
        float* o = AGG + (long)d0 * HDIM + lane * 4;
        asm volatile("red.global.add.v4.f32 [%0], {%1, %2, %3, %4};"
                     :: "l"(o), "f"(g0 * v0.x), "f"(g1 * v0.y),
                        "f"(g2 * v0.z), "f"(g3 * v0.w)
                     : "memory");
    }
    if (e0 + 1 < E) {
        const float g0 = 1.f / (1.f + __expf(-(k1.x + q1.x)));
        const float g1 = 1.f / (1.f + __expf(-(k1.y + q1.y)));
        const float g2 = 1.f / (1.f + __expf(-(k1.z + q1.z)));
        const float g3 = 1.f / (1.f + __expf(-(k1.w + q1.w)));
        float* o = AGG + (long)d1 * HDIM + lane * 4;
        asm volatile("red.global.add.v4.f32 [%0], {%1, %2, %3, %4};"
                     :: "l"(o), "f"(g0 * v1.x), "f"(g1 * v1.y),
                        "f"(g2 * v1.z), "f"(g3 * v1.w)
                     : "memory");
    }
}

// ---------------- pooling (proven) -----------------------------------------
__device__ __forceinline__ int lower_bound_i(const int* a, int n, int v) {
    int lo = 0, hi = n;
    while (lo < hi) { int m = (lo + hi) >> 1; if (a[m] < v) lo = m + 1; else hi = m; }
    return lo;
}

__global__ void pool_kernel(const float* __restrict__ H,
                            const int* __restrict__ batch, int N,
                            float* __restrict__ pool)
{
    const int g    = blockIdx.x;
    const int c    = blockIdx.y * 32 + (threadIdx.x & 31);
    const int rloc = threadIdx.x >> 5;          // 0..3
    const int lo = lower_bound_i(batch, N, g);
    const int hi = lower_bound_i(batch, N, g + 1);
    float mx = -3.402823466e38f;
    float sm = 0.f;
    for (int n = lo + rloc; n < hi; n += 4) {
        const float x = H[(long)n * HDIM + c];
        mx = fmaxf(mx, x);
        sm += x;
    }
    __shared__ float smx[4][32], ssm[4][32];
    smx[rloc][threadIdx.x & 31] = mx;
    ssm[rloc][threadIdx.x & 31] = sm;
    __syncthreads();
    if (rloc == 0) {
        const int l = threadIdx.x & 31;
        mx = fmaxf(fmaxf(smx[0][l], smx[1][l]), fmaxf(smx[2][l], smx[3][l]));
        sm = ssm[0][l] + ssm[1][l] + ssm[2][l] + ssm[3][l];
        const int cnt = hi - lo;
        pool[g * (2 * HDIM) + c]        = (cnt > 0) ? mx : 0.f;
        pool[g * (2 * HDIM) + HDIM + c] = sm / fmaxf((float)cnt, 1.f);
    }
}

// ---------------- MLP head (proven) ----------------------------------------
__global__ void mlp1_kernel(const float* __restrict__ pool,
                            const float* __restrict__ W1, const float* __restrict__ b1,
                            const float* __restrict__ g1, const float* __restrict__ be1,
                            float* __restrict__ h1)
{
    const int c = blockIdx.x;   // 0..127
    const int r = threadIdx.x;  // 0..63
    float acc = b1[c];
    const float* w = W1 + (long)c * (2 * HDIM);
    const float* f = pool + (long)r * (2 * HDIM);
#pragma unroll 8
    for (int i = 0; i < 2 * HDIM; i++) acc += f[i] * w[i];

    __shared__ float red[GNUM];
    red[r] = acc; __syncthreads();
    float m = 0.f;
    if (r == 0) { for (int i = 0; i < GNUM; i++) m += red[i]; red[0] = m / GNUM; }
    __syncthreads();
    m = red[0]; __syncthreads();
    red[r] = (acc - m) * (acc - m); __syncthreads();
    float v = 0.f;
    if (r == 0) { for (int i = 0; i < GNUM; i++) v += red[i]; red[0] = v / GNUM; }
    __syncthreads();
    v = red[0];
    const float y = g1[c] * (acc - m) * rsqrtf(v + EPSBN) + be1[c];
    h1[(long)r * HDIM + c] = fmaxf(y, 0.f);
}

__global__ void mlp2_kernel(const float* __restrict__ h1,
                            const float* __restrict__ W2, const float* __restrict__ b2,
                            const float* __restrict__ g2, const float* __restrict__ be2,
                            float* __restrict__ h2)
{
    const int c = blockIdx.x;   // 0..63
    const int r = threadIdx.x;  // 0..63
    float acc = b2[c];
    const float* w = W2 + (long)c * HDIM;
    const float* f = h1 + (long)r * HDIM;
#pragma unroll 8
    for (int i = 0; i < HDIM; i++) acc += f[i] * w[i];

    __shared__ float red[GNUM];
    red[r] = acc; __syncthreads();
    float m = 0.f;
    if (r == 0) { for (int i = 0; i < GNUM; i++) m += red[i]; red[0] = m / GNUM; }
    __syncthreads();
    m = red[0]; __syncthreads();
    red[r] = (acc - m) * (acc - m); __syncthreads();
    float v = 0.f;
    if (r == 0) { for (int i = 0; i < GNUM; i++) v += red[i]; red[0] = v / GNUM; }
    __syncthreads();
    v = red[0];
    const float y = g2[c] * (acc - m) * rsqrtf(v + EPSBN) + be2[c];
    h2[(long)r * (HDIM / 2) + c] = fmaxf(y, 0.f);
}

__global__ void mlp3_kernel(const float* __restrict__ h2,
                            const float* __restrict__ W3, const float* __restrict__ b3,
                            float* __restrict__ out)
{
    const int r = threadIdx.x;
    float acc = b3[0];
#pragma unroll
    for (int i = 0; i < HDIM / 2; i++) acc += h2[(long)r * (HDIM / 2) + i] * W3[i];
    out[r] = acc;
}

// ---------------- launch -----------------
extern "C" void kernel_launch(void* const* d_in, const int* in_sizes, int n_in,
                              void* d_out, int out_size)
{
    const float* x     = (const float*)d_in[0];
    const int*   ei    = (const int*)d_in[1];
    const int*   batch = (const int*)d_in[2];
    const int N = in_sizes[0] / HDIM;
    const int E = in_sizes[1] / 2;

    const float* l0W[4], *l0b[4], *l1W[4], *l1b[4];
    for (int i = 0; i < 4; i++) {
        l0W[i] = (const float*)d_in[3 + 2 * i];
        l0b[i] = (const float*)d_in[4 + 2 * i];
        l1W[i] = (const float*)d_in[11 + 2 * i];
        l1b[i] = (const float*)d_in[12 + 2 * i];
    }
    const float* W1  = (const float*)d_in[19];
    const float* b1  = (const float*)d_in[20];
    const float* g1  = (const float*)d_in[21];
    const float* be1 = (const float*)d_in[22];
    const float* W2  = (const float*)d_in[23];
    const float* b2  = (const float*)d_in[24];
    const float* g2  = (const float*)d_in[25];
    const float* be2 = (const float*)d_in[26];
    const float* W3  = (const float*)d_in[27];
    const float* b3  = (const float*)d_in[28];
    float* out = (float*)d_out;

    float *pK, *pQ, *pV, *pH0, *pH1, *pPool, *pM1, *pM2;
    uint32_t *pBFH, *pBFL;
    cudaGetSymbolAddress((void**)&pK,  g_K);
    cudaGetSymbolAddress((void**)&pQ,  g_Q);
    cudaGetSymbolAddress((void**)&pV,  g_V);
    cudaGetSymbolAddress((void**)&pH0, g_H0);
    cudaGetSymbolAddress((void**)&pH1, g_H1);
    cudaGetSymbolAddress((void**)&pPool, g_pool);
    cudaGetSymbolAddress((void**)&pM1, g_h1m);
    cudaGetSymbolAddress((void**)&pM2, g_h2m);
    cudaGetSymbolAddress((void**)&pBFH, g_BFHg);
    cudaGetSymbolAddress((void**)&pBFL, g_BFLg);

    // dynamic smem: A frags (64 KB) + 2 B stages (40 KB) = 104 KB
    const int gsmem = (2 * 8192 + 2 * 5120) * 4;   // 106496 B
    cudaFuncSetAttribute(gemm_bf16x3_kernel<false>,
                         cudaFuncAttributeMaxDynamicSharedMemorySize, gsmem);
    cudaFuncSetAttribute(gemm_bf16x3_kernel<true>,
                         cudaFuncAttributeMaxDynamicSharedMemorySize, gsmem);

    const dim3 ggrid((N + 127) / 128, 2);
    const int eblocks = (E + 15) / 16;   // 8 warps/block, 2 edges per warp

    // prep: frag-ordered weight split (64 blocks: 8 sel x 8 row-slices)
    split_wfrag_kernel<<<64, 256>>>(
        l0W[0], l0W[1], l0W[2], l0W[3], l1W[0], l1W[1], l1W[2], l1W[3], pBFH, pBFL);

    // layer 0
    gemm_bf16x3_kernel<false><<<ggrid, 256, gsmem>>>(x, pBFH, pBFL,
        l0b[0], l0b[1], l0b[2], l0b[3], pK, pQ, pV, pH0, N, 0);
    edge_kernel<<<eblocks, 256>>>(ei, E, pK, pQ, pV, pH0);
    // layer 1 (relu on input), weights slots 4..7
    gemm_bf16x3_kernel<true><<<ggrid, 256, gsmem>>>(pH0, pBFH, pBFL,
        l1b[0], l1b[1], l1b[2], l1b[3], pK, pQ, pV, pH1, N, 4);
    edge_kernel<<<eblocks, 256>>>(ei, E, pK, pQ, pV, pH1);
    // pooling + head (proven)
    pool_kernel<<<dim3(GNUM, 4), 128>>>(pH1, batch, N, pPool);
    mlp1_kernel<<<HDIM, GNUM>>>(pPool, W1, b1, g1, be1, pM1);
    mlp2_kernel<<<HDIM / 2, GNUM>>>(pM1, W2, b2, g2, be2, pM2);
    mlp3_kernel<<<1, GNUM>>>(pM2, W3, b3, out);
}

// round 14
// speedup vs baseline: 1.0107x; 1.0107x over previous
#include <cuda_runtime.h>
#include <cuda_bf16.h>
#include <cstdint>

#define NNODE 50000
#define HDIM  128
#define GNUM  64
#define EPSBN 1e-5f

// ---------------- device scratch (no allocs allowed) ----------------
__device__ float g_K [NNODE * HDIM];
__device__ float g_Q [NNODE * HDIM];
__device__ float g_V [NNODE * HDIM];
__device__ float g_H0[NNODE * HDIM];
__device__ float g_H1[NNODE * HDIM];
__device__ float g_pool[GNUM * 2 * HDIM];
__device__ float g_h1m[GNUM * HDIM];
__device__ float g_h2m[GNUM * (HDIM / 2)];
// pre-split frag-ordered weights: [sel 0..7][kt 0..3][2560 u32]
__device__ uint32_t g_BFHg[8 * 4 * 2560];
__device__ uint32_t g_BFLg[8 * 4 * 2560];

// ---------------- bf16 split helpers ----------------
__device__ __forceinline__ void split2(float x, float y, uint32_t& hi, uint32_t& lo) {
    __nv_bfloat162 h = __floats2bfloat162_rn(x, y);
    float hx = __bfloat162float(h.x);
    float hy = __bfloat162float(h.y);
    __nv_bfloat162 l = __floats2bfloat162_rn(x - hx, y - hy);
    hi = *(uint32_t*)&h;
    lo = *(uint32_t*)&l;
}

__device__ __forceinline__ void mma_bf16(float c[4], const uint32_t a[4], const uint32_t b[2]) {
    asm volatile(
        "mma.sync.aligned.m16n8k16.row.col.f32.bf16.bf16.f32 "
        "{%0,%1,%2,%3}, {%4,%5,%6,%7}, {%8,%9}, {%0,%1,%2,%3};"
        : "+f"(c[0]), "+f"(c[1]), "+f"(c[2]), "+f"(c[3])
        : "r"(a[0]), "r"(a[1]), "r"(a[2]), "r"(a[3]), "r"(b[0]), "r"(b[1]));
}

// lane permutation to de-alias writer banks; readers apply identically
__device__ __forceinline__ int PERM(int l) { return l ^ ((l & 8) >> 3); }

__device__ __forceinline__ void cp_async16(uint32_t smem_addr, const void* gptr) {
    asm volatile("cp.async.ca.shared.global [%0], [%1], 16;"
                 :: "r"(smem_addr), "l"(gptr));
}

// ---------------- prep: split 8 weight matrices into frag-ordered gmem -----
__global__ void split_wfrag_kernel(
    const float* __restrict__ w0, const float* __restrict__ w1,
    const float* __restrict__ w2, const float* __restrict__ w3,
    const float* __restrict__ w4, const float* __restrict__ w5,
    const float* __restrict__ w6, const float* __restrict__ w7,
    uint32_t* __restrict__ BH, uint32_t* __restrict__ BL)
{
    const int sel   = blockIdx.x >> 3;
    const int slice = blockIdx.x & 7;        // 16-row slice
    const float* w = (sel == 0) ? w0 : (sel == 1) ? w1 : (sel == 2) ? w2 : (sel == 3) ? w3
                   : (sel == 4) ? w4 : (sel == 5) ? w5 : (sel == 6) ? w6 : w7;
    const int tid = threadIdx.x;
#pragma unroll
    for (int it = 0; it < 2; it++) {
        const int idx = tid + it * 256;      // 0..511
        const int n   = slice * 16 + (idx >> 5);   // row 0..127
        const int c4g = (idx & 31) * 4;      // global k offset 0..124
        const float4 b = *(const float4*)(w + (long)n * HDIM + c4g);
        uint32_t h0, l0, h1, l1;
        split2(b.x, b.y, h0, l0);
        split2(b.z, b.w, h1, l1);
        const int kt  = c4g >> 5;
        const int c4l = c4g & 31;
        const int bwn = n >> 6;
        const int c64 = n & 63;
        const int nt  = c64 >> 3;
        const int btp = c64 & 7;
#pragma unroll
        for (int u = 0; u < 2; u++) {
            const int kp  = (c4l >> 1) + u;
            const int ks  = kp >> 3;
            const int kp8 = kp & 7;
            const int wl  = PERM(btp * 4 + (kp8 & 3));
            const int reg = kp8 >> 2;
            const long bi = (long)(sel * 4 + kt) * 2560
                          + ((bwn * 2 + ks) * 32 + wl) * 20 + nt * 2 + reg;
            BH[bi] = (u == 0) ? h0 : h1;
            BL[bi] = (u == 0) ? l0 : l1;
        }
    }
}

// ---------------- bf16x3 GEMM (R12 shell) + cp.async-staged raw A ----------
// grid = (ceil(N/128), 4 weight-select), 256 threads (8 warps).
// BM=128, BN=128, BK=32. Warp tile 32x64 via m16n8k16, hi/lo split.
// dynamic smem (u32): [AFH 2048][AFL 2048][BH 10240][BL 10240][rawA 4096]
// = 28672 u32 = 112 KB -> 2 blocks/SM.
template <bool RELU_IN>
__global__ __launch_bounds__(256) void gemm_bf16x3_kernel(
    const float* __restrict__ X,
    const uint32_t* __restrict__ BFHg, const uint32_t* __restrict__ BFLg,
    const float* __restrict__ bk, const float* __restrict__ bq,
    const float* __restrict__ bv, const float* __restrict__ bs,
    float* __restrict__ oK, float* __restrict__ oQ,
    float* __restrict__ oV, float* __restrict__ oS, int N, int wbase)
{
    extern __shared__ uint32_t smem[];
    uint32_t* AFH = smem;
    uint32_t* AFL = smem + 2048;
    uint32_t* BH  = smem + 4096;
    uint32_t* BL  = smem + 14336;
    float*    RAW = (float*)(smem + 24576);   // 4096 floats (one 128x32 tile)

    const int sel = blockIdx.y;
    const float* bias = (sel == 0) ? bk : (sel == 1) ? bq : (sel == 2) ? bv : bs;
    float*       out  = (sel == 0) ? oK : (sel == 1) ? oQ : (sel == 2) ? oV : oS;
    const int m0 = blockIdx.x * 128;

    const int tid  = threadIdx.x;
    const int wid  = tid >> 5;
    const int lane = tid & 31;
    const int wm   = wid & 3;        // 0..3 -> 32-row slab
    const int wn   = wid >> 2;       // 0..1 -> 64-col slab
    const int tig  = lane & 3;
    const int tp   = lane >> 2;
    const int pl   = PERM(lane);

    // raw-A copy: 1024 float4 chunks, 4 per thread. OOB rows clamp to row 0
    // of the tile (value irrelevant: epilogue masks those output rows, and
    // frags from garbage rows only feed masked outputs).
    auto load_rawA = [&](int k0) {
#pragma unroll
        for (int j = 0; j < 4; j++) {
            const int c   = tid + j * 256;        // chunk 0..1023
            const int row = c >> 3;               // 0..127
            const int c4  = (c & 7) * 4;
            const int gm  = m0 + row;
            const float* src = X + (long)((gm < N) ? gm : m0) * HDIM + k0 + c4;
            cp_async16((uint32_t)__cvta_generic_to_shared(RAW + row * 32 + c4), src);
        }
        asm volatile("cp.async.commit_group;" ::: "memory");
    };

    // ---- issue all B copies (5120 chunks of 16 B, 20 per thread) ----
    {
        const uint32_t* gBH = BFHg + (long)(wbase + sel) * 4 * 2560;
        const uint32_t* gBL = BFLg + (long)(wbase + sel) * 4 * 2560;
#pragma unroll
        for (int i = 0; i < 20; i++) {
            const int c = tid + i * 256;     // 0..5119
            if (c < 2560) {
                cp_async16((uint32_t)__cvta_generic_to_shared(&BH[c * 4]), gBH + c * 4);
            } else {
                const int c2 = c - 2560;
                cp_async16((uint32_t)__cvta_generic_to_shared(&BL[c2 * 4]), gBL + c2 * 4);
            }
        }
        asm volatile("cp.async.commit_group;" ::: "memory");
    }
    load_rawA(0);
    asm volatile("cp.async.wait_group 0;" ::: "memory");
    __syncthreads();

    float c[2][8][4];
#pragma unroll
    for (int mt = 0; mt < 2; mt++)
#pragma unroll
        for (int nt = 0; nt < 8; nt++)
#pragma unroll
            for (int j = 0; j < 4; j++) c[mt][nt][j] = 0.f;

    for (int k0 = 0; k0 < HDIM; k0 += 32) {
        const int kt = k0 >> 5;
        // ---- split raw A (smem) into fragment-ordered smem ----
#pragma unroll
        for (int it = 0; it < 4; it++) {
            const int idx = tid + it * 256;       // 0..1023
            const int row = idx >> 3;
            const int c4  = (idx & 7) * 4;        // k offset in tile
            float4 a = *(const float4*)(RAW + row * 32 + c4);
            const int gm  = m0 + row;
            if (gm >= N) a = make_float4(0.f, 0.f, 0.f, 0.f);
            if (RELU_IN) {
                a.x = fmaxf(a.x, 0.f); a.y = fmaxf(a.y, 0.f);
                a.z = fmaxf(a.z, 0.f); a.w = fmaxf(a.w, 0.f);
            }
            uint32_t h0, l0, h1, l1;
            split2(a.x, a.y, h0, l0);
            split2(a.z, a.w, h1, l1);
            const int awm = row >> 5;
            const int amt = (row >> 4) & 1;
            const int r16 = row & 15;
            const int atp = r16 & 7;
            const int jrow = r16 >> 3;
#pragma unroll
            for (int u = 0; u < 2; u++) {
                const int kp  = (c4 >> 1) + u;
                const int ks  = kp >> 3;
                const int kp8 = kp & 7;
                const int wl  = PERM(atp * 4 + (kp8 & 3));
                const int j   = jrow + ((kp8 >> 2) << 1);
                const int ai  = (((awm * 2 + amt) * 2 + ks) * 32 + wl) * 4 + j;
                AFH[ai] = (u == 0) ? h0 : h1;
                AFL[ai] = (u == 0) ? l0 : l1;
            }
        }
        __syncthreads();   // frags built; RAW fully consumed
        if (kt < 3) load_rawA(k0 + 32);   // prefetch next raw tile under compute

#pragma unroll
        for (int ks = 0; ks < 2; ks++) {
            uint32_t ah[2][4], al[2][4];
#pragma unroll
            for (int mt = 0; mt < 2; mt++) {
                const uint32_t base = (((wm * 2 + mt) * 2 + ks) * 32 + pl) * 4;
                uint4 th = *(const uint4*)&AFH[base];
                uint4 tl = *(const uint4*)&AFL[base];
                ah[mt][0] = th.x; ah[mt][1] = th.y; ah[mt][2] = th.z; ah[mt][3] = th.w;
                al[mt][0] = tl.x; al[mt][1] = tl.y; al[mt][2] = tl.z; al[mt][3] = tl.w;
            }
            uint32_t bhw[16], blw[16];
            {
                const uint32_t base = kt * 2560 + ((wn * 2 + ks) * 32 + pl) * 20;
#pragma unroll
                for (int q = 0; q < 4; q++) {
                    uint4 th = *(const uint4*)&BH[base + q * 4];
                    bhw[q * 4 + 0] = th.x; bhw[q * 4 + 1] = th.y;
                    bhw[q * 4 + 2] = th.z; bhw[q * 4 + 3] = th.w;
                    uint4 tl = *(const uint4*)&BL[base + q * 4];
                    blw[q * 4 + 0] = tl.x; blw[q * 4 + 1] = tl.y;
                    blw[q * 4 + 2] = tl.z; blw[q * 4 + 3] = tl.w;
                }
            }
#pragma unroll
            for (int mt = 0; mt < 2; mt++)
#pragma unroll
                for (int nt = 0; nt < 8; nt++) {
                    const uint32_t bh2[2] = {bhw[2 * nt], bhw[2 * nt + 1]};
                    const uint32_t bl2[2] = {blw[2 * nt], blw[2 * nt + 1]};
                    mma_bf16(c[mt][nt], ah[mt], bl2);   // cross terms
                    mma_bf16(c[mt][nt], al[mt], bh2);
                    mma_bf16(c[mt][nt], ah[mt], bh2);   // main term
                }
        }
        if (kt < 3) asm volatile("cp.async.wait_group 0;" ::: "memory");
        __syncthreads();   // frags consumed; raw(kt+1) landed
    }

    // epilogue: bias add + store (identical to R12)
#pragma unroll
    for (int nt = 0; nt < 8; nt++) {
        const int col = wn * 64 + nt * 8 + 2 * tig;
        const float b0 = bias[col];
        const float b1 = bias[col + 1];
#pragma unroll
        for (int mt = 0; mt < 2; mt++) {
            const int r0 = m0 + wm * 32 + mt * 16 + tp;
            const int r1 = r0 + 8;
            if (r0 < N) {
                float2 v = make_float2(c[mt][nt][0] + b0, c[mt][nt][1] + b1);
                *(float2*)(out + (long)r0 * HDIM + col) = v;
            }
            if (r1 < N) {
                float2 v = make_float2(c[mt][nt][2] + b0, c[mt][nt][3] + b1);
                *(float2*)(out + (long)r1 * HDIM + col) = v;
            }
        }
    }
}

// ---------------- edge kernel: 2 edges per warp, phase-split (R6-proven) ---
__global__ __launch_bounds__(256) void edge_kernel(
    const int* __restrict__ ei, int E,
    const float* __restrict__ K, const float* __restrict__ Q,
    const float* __restrict__ V, float* __restrict__ AGG)
{
    const int w    = (blockIdx.x * blockDim.x + threadIdx.x) >> 5;
    const int lane = threadIdx.x & 31;
    const int e0   = w * 2;
    if (e0 >= E) return;
    const int e1   = (e0 + 1 < E) ? e0 + 1 : e0;

    const int s0 = __ldg(ei + e0);
    const int s1 = __ldg(ei + e1);
    const int d0 = __ldg(ei + E + e0);
    const int d1 = __ldg(ei + E + e1);

    const float4 k0 = *(const float4*)(K + (long)d0 * HDIM + lane * 4);
    const float4 q0 = *(const float4*)(Q + (long)s0 * HDIM + lane * 4);
    const float4 v0 = *(const float4*)(V + (long)s0 * HDIM + lane * 4);
    const float4 k1 = *(const float4*)(K + (long)d1 * HDIM + lane * 4);
    const float4 q1 = *(const float4*)(Q + (long)s1 * HDIM + lane * 4);
    const float4 v1 = *(const float4*)(V + (long)s1 * HDIM + lane * 4);

    {
        const float g0 = 1.f / (1.f + __expf(-(k0.x + q0.x)));
        const float g1 = 1.f / (1.f + __expf(-(k0.y + q0.y)));
        const float g2 = 1.f / (1.f + __expf(-(k0.z + q0.z)));
        const float g3 = 1.f / (1.f + __expf(-(k0.w + q0.w)));
        float* o = AGG + (long)d0 * HDIM + lane * 4;
        asm volatile("red.global.add.v4.f32 [%0], {%1, %2, %3, %4};"
                     :: "l"(o), "f"(g0 * v0.x), "f"(g1 * v0.y),
                        "f"(g2 * v0.z), "f"(g3 * v0.w)
                     : "memory");
    }
    if (e0 + 1 < E) {
        const float g0 = 1.f / (1.f + __expf(-(k1.x + q1.x)));
        const float g1 = 1.f / (1.f + __expf(-(k1.y + q1.y)));
        const float g2 = 1.f / (1.f + __expf(-(k1.z + q1.z)));
        const float g3 = 1.f / (1.f + __expf(-(k1.w + q1.w)));
        float* o = AGG + (long)d1 * HDIM + lane * 4;
        asm volatile("red.global.add.v4.f32 [%0], {%1, %2, %3, %4};"
                     :: "l"(o), "f"(g0 * v1.x), "f"(g1 * v1.y),
                        "f"(g2 * v1.z), "f"(g3 * v1.w)
                     : "memory");
    }
}

// ---------------- pooling (proven) -----------------------------------------
__device__ __forceinline__ int lower_bound_i(const int* a, int n, int v) {
    int lo = 0, hi = n;
    while (lo < hi) { int m = (lo + hi) >> 1; if (a[m] < v) lo = m + 1; else hi = m; }
    return lo;
}

__global__ void pool_kernel(const float* __restrict__ H,
                            const int* __restrict__ batch, int N,
                            float* __restrict__ pool)
{
    const int g    = blockIdx.x;
    const int c    = blockIdx.y * 32 + (threadIdx.x & 31);
    const int rloc = threadIdx.x >> 5;          // 0..3
    const int lo = lower_bound_i(batch, N, g);
    const int hi = lower_bound_i(batch, N, g + 1);
    float mx = -3.402823466e38f;
    float sm = 0.f;
    for (int n = lo + rloc; n < hi; n += 4) {
        const float x = H[(long)n * HDIM + c];
        mx = fmaxf(mx, x);
        sm += x;
    }
    __shared__ float smx[4][32], ssm[4][32];
    smx[rloc][threadIdx.x & 31] = mx;
    ssm[rloc][threadIdx.x & 31] = sm;
    __syncthreads();
    if (rloc == 0) {
        const int l = threadIdx.x & 31;
        mx = fmaxf(fmaxf(smx[0][l], smx[1][l]), fmaxf(smx[2][l], smx[3][l]));
        sm = ssm[0][l] + ssm[1][l] + ssm[2][l] + ssm[3][l];
        const int cnt = hi - lo;
        pool[g * (2 * HDIM) + c]        = (cnt > 0) ? mx : 0.f;
        pool[g * (2 * HDIM) + HDIM + c] = sm / fmaxf((float)cnt, 1.f);
    }
}

// ---------------- MLP head (proven) ----------------------------------------
__global__ void mlp1_kernel(const float* __restrict__ pool,
                            const float* __restrict__ W1, const float* __restrict__ b1,
                            const float* __restrict__ g1, const float* __restrict__ be1,
                            float* __restrict__ h1)
{
    const int c = blockIdx.x;   // 0..127
    const int r = threadIdx.x;  // 0..63
    float acc = b1[c];
    const float* w = W1 + (long)c * (2 * HDIM);
    const float* f = pool + (long)r * (2 * HDIM);
#pragma unroll 8
    for (int i = 0; i < 2 * HDIM; i++) acc += f[i] * w[i];

    __shared__ float red[GNUM];
    red[r] = acc; __syncthreads();
    float m = 0.f;
    if (r == 0) { for (int i = 0; i < GNUM; i++) m += red[i]; red[0] = m / GNUM; }
    __syncthreads();
    m = red[0]; __syncthreads();
    red[r] = (acc - m) * (acc - m); __syncthreads();
    float v = 0.f;
    if (r == 0) { for (int i = 0; i < GNUM; i++) v += red[i]; red[0] = v / GNUM; }
    __syncthreads();
    v = red[0];
    const float y = g1[c] * (acc - m) * rsqrtf(v + EPSBN) + be1[c];
    h1[(long)r * HDIM + c] = fmaxf(y, 0.f);
}

__global__ void mlp2_kernel(const float* __restrict__ h1,
                            const float* __restrict__ W2, const float* __restrict__ b2,
                            const float* __restrict__ g2, const float* __restrict__ be2,
                            float* __restrict__ h2)
{
    const int c = blockIdx.x;   // 0..63
    const int r = threadIdx.x;  // 0..63
    float acc = b2[c];
    const float* w = W2 + (long)c * HDIM;
    const float* f = h1 + (long)r * HDIM;
#pragma unroll 8
    for (int i = 0; i < HDIM; i++) acc += f[i] * w[i];

    __shared__ float red[GNUM];
    red[r] = acc; __syncthreads();
    float m = 0.f;
    if (r == 0) { for (int i = 0; i < GNUM; i++) m += red[i]; red[0] = m / GNUM; }
    __syncthreads();
    m = red[0]; __syncthreads();
    red[r] = (acc - m) * (acc - m); __syncthreads();
    float v = 0.f;
    if (r == 0) { for (int i = 0; i < GNUM; i++) v += red[i]; red[0] = v / GNUM; }
    __syncthreads();
    v = red[0];
    const float y = g2[c] * (acc - m) * rsqrtf(v + EPSBN) + be2[c];
    h2[(long)r * (HDIM / 2) + c] = fmaxf(y, 0.f);
}

__global__ void mlp3_kernel(const float* __restrict__ h2,
                            const float* __restrict__ W3, const float* __restrict__ b3,
                            float* __restrict__ out)
{
    const int r = threadIdx.x;
    float acc = b3[0];
#pragma unroll
    for (int i = 0; i < HDIM / 2; i++) acc += h2[(long)r * (HDIM / 2) + i] * W3[i];
    out[r] = acc;
}

// ---------------- launch -----------------
extern "C" void kernel_launch(void* const* d_in, const int* in_sizes, int n_in,
                              void* d_out, int out_size)
{
    const float* x     = (const float*)d_in[0];
    const int*   ei    = (const int*)d_in[1];
    const int*   batch = (const int*)d_in[2];
    const int N = in_sizes[0] / HDIM;
    const int E = in_sizes[1] / 2;

    const float* l0W[4], *l0b[4], *l1W[4], *l1b[4];
    for (int i = 0; i < 4; i++) {
        l0W[i] = (const float*)d_in[3 + 2 * i];
        l0b[i] = (const float*)d_in[4 + 2 * i];
        l1W[i] = (const float*)d_in[11 + 2 * i];
        l1b[i] = (const float*)d_in[12 + 2 * i];
    }
    const float* W1  = (const float*)d_in[19];
    const float* b1  = (const float*)d_in[20];
    const float* g1  = (const float*)d_in[21];
    const float* be1 = (const float*)d_in[22];
    const float* W2  = (const float*)d_in[23];
    const float* b2  = (const float*)d_in[24];
    const float* g2  = (const float*)d_in[25];
    const float* be2 = (const float*)d_in[26];
    const float* W3  = (const float*)d_in[27];
    const float* b3  = (const float*)d_in[28];
    float* out = (float*)d_out;

    float *pK, *pQ, *pV, *pH0, *pH1, *pPool, *pM1, *pM2;
    uint32_t *pBFH, *pBFL;
    cudaGetSymbolAddress((void**)&pK,  g_K);
    cudaGetSymbolAddress((void**)&pQ,  g_Q);
    cudaGetSymbolAddress((void**)&pV,  g_V);
    cudaGetSymbolAddress((void**)&pH0, g_H0);
    cudaGetSymbolAddress((void**)&pH1, g_H1);
    cudaGetSymbolAddress((void**)&pPool, g_pool);
    cudaGetSymbolAddress((void**)&pM1, g_h1m);
    cudaGetSymbolAddress((void**)&pM2, g_h2m);
    cudaGetSymbolAddress((void**)&pBFH, g_BFHg);
    cudaGetSymbolAddress((void**)&pBFL, g_BFLg);

    // dynamic smem: A frags 16 KB + B 80 KB + raw A 16 KB = 112 KB
    const int gsmem = 28672 * 4;
    cudaFuncSetAttribute(gemm_bf16x3_kernel<false>,
                         cudaFuncAttributeMaxDynamicSharedMemorySize, gsmem);
    cudaFuncSetAttribute(gemm_bf16x3_kernel<true>,
                         cudaFuncAttributeMaxDynamicSharedMemorySize, gsmem);

    const dim3 ggrid((N + 127) / 128, 4);
    const int eblocks = (E + 15) / 16;   // 8 warps/block, 2 edges per warp

    // prep: frag-ordered weight split (64 blocks: 8 sel x 8 row-slices)
    split_wfrag_kernel<<<64, 256>>>(
        l0W[0], l0W[1], l0W[2], l0W[3], l1W[0], l1W[1], l1W[2], l1W[3], pBFH, pBFL);

    // layer 0
    gemm_bf16x3_kernel<false><<<ggrid, 256, gsmem>>>(x, pBFH, pBFL,
        l0b[0], l0b[1], l0b[2], l0b[3], pK, pQ, pV, pH0, N, 0);
    edge_kernel<<<eblocks, 256>>>(ei, E, pK, pQ, pV, pH0);
    // layer 1 (relu on input), weights slots 4..7
    gemm_bf16x3_kernel<true><<<ggrid, 256, gsmem>>>(pH0, pBFH, pBFL,
        l1b[0], l1b[1], l1b[2], l1b[3], pK, pQ, pV, pH1, N, 4);
    edge_kernel<<<eblocks, 256>>>(ei, E, pK, pQ, pV, pH1);
    // pooling + head (proven)
    pool_kernel<<<dim3(GNUM, 4), 128>>>(pH1, batch, N, pPool);
    mlp1_kernel<<<HDIM, GNUM>>>(pPool, W1, b1, g1, be1, pM1);
    mlp2_kernel<<<HDIM / 2, GNUM>>>(pM1, W2, b2, g2, be2, pM2);
    mlp3_kernel<<<1, GNUM>>>(pM2, W3, b3, out);
}

// round 15
// speedup vs baseline: 1.0534x; 1.0422x over previous
#include <cuda_runtime.h>
#include <cuda_bf16.h>
#include <cstdint>

#define NNODE 50000
#define HDIM  128
#define GNUM  64
#define EPSBN 1e-5f

// ---------------- device scratch (no allocs allowed) ----------------
__device__ float g_K [NNODE * HDIM];
__device__ float g_Q [NNODE * HDIM];
__device__ float g_V [NNODE * HDIM];
__device__ float g_H0[NNODE * HDIM];
__device__ float g_H1[NNODE * HDIM];
__device__ float g_pool[GNUM * 2 * HDIM];
__device__ float g_h1m[GNUM * HDIM];
__device__ float g_h2m[GNUM * (HDIM / 2)];
// pre-split frag-ordered weights: [sel 0..7][kt 0..3][2560 u32]
__device__ uint32_t g_BFHg[8 * 4 * 2560];
__device__ uint32_t g_BFLg[8 * 4 * 2560];

// ---------------- bf16 split helpers ----------------
__device__ __forceinline__ void split2(float x, float y, uint32_t& hi, uint32_t& lo) {
    __nv_bfloat162 h = __floats2bfloat162_rn(x, y);
    float hx = __bfloat162float(h.x);
    float hy = __bfloat162float(h.y);
    __nv_bfloat162 l = __floats2bfloat162_rn(x - hx, y - hy);
    hi = *(uint32_t*)&h;
    lo = *(uint32_t*)&l;
}

__device__ __forceinline__ void mma_bf16(float c[4], const uint32_t a[4], const uint32_t b[2]) {
    asm volatile(
        "mma.sync.aligned.m16n8k16.row.col.f32.bf16.bf16.f32 "
        "{%0,%1,%2,%3}, {%4,%5,%6,%7}, {%8,%9}, {%0,%1,%2,%3};"
        : "+f"(c[0]), "+f"(c[1]), "+f"(c[2]), "+f"(c[3])
        : "r"(a[0]), "r"(a[1]), "r"(a[2]), "r"(a[3]), "r"(b[0]), "r"(b[1]));
}

// lane permutation to de-alias writer banks; readers apply identically
__device__ __forceinline__ int PERM(int l) { return l ^ ((l & 8) >> 3); }

__device__ __forceinline__ void cp_async16(uint32_t smem_addr, const void* gptr) {
    asm volatile("cp.async.ca.shared.global [%0], [%1], 16;"
                 :: "r"(smem_addr), "l"(gptr));
}

// ---------------- prep: split 8 weight matrices into frag-ordered gmem -----
__global__ void split_wfrag_kernel(
    const float* __restrict__ w0, const float* __restrict__ w1,
    const float* __restrict__ w2, const float* __restrict__ w3,
    const float* __restrict__ w4, const float* __restrict__ w5,
    const float* __restrict__ w6, const float* __restrict__ w7,
    uint32_t* __restrict__ BH, uint32_t* __restrict__ BL)
{
    const int sel   = blockIdx.x >> 3;
    const int slice = blockIdx.x & 7;        // 16-row slice
    const float* w = (sel == 0) ? w0 : (sel == 1) ? w1 : (sel == 2) ? w2 : (sel == 3) ? w3
                   : (sel == 4) ? w4 : (sel == 5) ? w5 : (sel == 6) ? w6 : w7;
    const int tid = threadIdx.x;
#pragma unroll
    for (int it = 0; it < 2; it++) {
        const int idx = tid + it * 256;      // 0..511
        const int n   = slice * 16 + (idx >> 5);   // row 0..127
        const int c4g = (idx & 31) * 4;      // global k offset 0..124
        const float4 b = *(const float4*)(w + (long)n * HDIM + c4g);
        uint32_t h0, l0, h1, l1;
        split2(b.x, b.y, h0, l0);
        split2(b.z, b.w, h1, l1);
        const int kt  = c4g >> 5;
        const int c4l = c4g & 31;
        const int bwn = n >> 6;
        const int c64 = n & 63;
        const int nt  = c64 >> 3;
        const int btp = c64 & 7;
#pragma unroll
        for (int u = 0; u < 2; u++) {
            const int kp  = (c4l >> 1) + u;
            const int ks  = kp >> 3;
            const int kp8 = kp & 7;
            const int wl  = PERM(btp * 4 + (kp8 & 3));
            const int reg = kp8 >> 2;
            const long bi = (long)(sel * 4 + kt) * 2560
                          + ((bwn * 2 + ks) * 32 + wl) * 20 + nt * 2 + reg;
            BH[bi] = (u == 0) ? h0 : h1;
            BL[bi] = (u == 0) ? l0 : l1;
        }
    }
}

// ---------------- bf16x3 GEMM (R12-proven: frag smem + pre-split B) --------
// grid = (ceil(N/128), 4 weight-select), 256 threads (8 warps).
// BM=128, BN=128, BK=32. Warp tile 32x64 via m16n8k16, hi/lo split.
template <bool RELU_IN>
__global__ __launch_bounds__(256) void gemm_bf16x3_kernel(
    const float* __restrict__ X,
    const uint32_t* __restrict__ BFHg, const uint32_t* __restrict__ BFLg,
    const float* __restrict__ bk, const float* __restrict__ bq,
    const float* __restrict__ bv, const float* __restrict__ bs,
    float* __restrict__ oK, float* __restrict__ oQ,
    float* __restrict__ oV, float* __restrict__ oS, int N, int wbase)
{
    const int sel = blockIdx.y;
    const float* bias = (sel == 0) ? bk : (sel == 1) ? bq : (sel == 2) ? bv : bs;
    float*       out  = (sel == 0) ? oK : (sel == 1) ? oQ : (sel == 2) ? oV : oS;
    const int m0 = blockIdx.x * 128;

    __shared__ uint32_t AFH[2048], AFL[2048];   // A frags (one k-tile)
    extern __shared__ uint32_t bdyn[];          // B frags: [kt][2560] H then L
    uint32_t* BH = bdyn;                        // 4*2560
    uint32_t* BL = bdyn + 4 * 2560;

    const int tid  = threadIdx.x;
    const int wid  = tid >> 5;
    const int lane = tid & 31;
    const int wm   = wid & 3;        // 0..3 -> 32-row slab
    const int wn   = wid >> 2;       // 0..1 -> 64-col slab
    const int tig  = lane & 3;
    const int tp   = lane >> 2;
    const int pl   = PERM(lane);

    // ---- issue all B copies up front (5120 chunks of 16 B, 20 per thread) --
    {
        const uint32_t* gBH = BFHg + (long)(wbase + sel) * 4 * 2560;
        const uint32_t* gBL = BFLg + (long)(wbase + sel) * 4 * 2560;
#pragma unroll
        for (int i = 0; i < 20; i++) {
            const int c = tid + i * 256;     // 0..5119
            if (c < 2560) {
                cp_async16((uint32_t)__cvta_generic_to_shared(&BH[c * 4]), gBH + c * 4);
            } else {
                const int c2 = c - 2560;
                cp_async16((uint32_t)__cvta_generic_to_shared(&BL[c2 * 4]), gBL + c2 * 4);
            }
        }
        asm volatile("cp.async.commit_group;" ::: "memory");
    }

    float c[2][8][4];
#pragma unroll
    for (int mt = 0; mt < 2; mt++)
#pragma unroll
        for (int nt = 0; nt < 8; nt++)
#pragma unroll
            for (int j = 0; j < 4; j++) c[mt][nt][j] = 0.f;

    for (int k0 = 0; k0 < HDIM; k0 += 32) {
        const int kt = k0 >> 5;
        // ---- load + split A tile into fragment-ordered smem ----
#pragma unroll
        for (int it = 0; it < 4; it++) {
            const int idx = tid + it * 256;       // 0..1023
            const int row = idx >> 3;
            const int c4  = (idx & 7) * 4;        // k offset in tile
            const int gm  = m0 + row;
            float4 a = make_float4(0.f, 0.f, 0.f, 0.f);
            if (gm < N) a = *(const float4*)(X + (long)gm * HDIM + k0 + c4);
            if (RELU_IN) {
                a.x = fmaxf(a.x, 0.f); a.y = fmaxf(a.y, 0.f);
                a.z = fmaxf(a.z, 0.f); a.w = fmaxf(a.w, 0.f);
            }
            uint32_t h0, l0, h1, l1;
            split2(a.x, a.y, h0, l0);
            split2(a.z, a.w, h1, l1);
            const int awm = row >> 5;
            const int amt = (row >> 4) & 1;
            const int r16 = row & 15;
            const int atp = r16 & 7;
            const int jrow = r16 >> 3;
#pragma unroll
            for (int u = 0; u < 2; u++) {
                const int kp  = (c4 >> 1) + u;
                const int ks  = kp >> 3;
                const int kp8 = kp & 7;
                const int wl  = PERM(atp * 4 + (kp8 & 3));
                const int j   = jrow + ((kp8 >> 2) << 1);
                const int ai  = (((awm * 2 + amt) * 2 + ks) * 32 + wl) * 4 + j;
                AFH[ai] = (u == 0) ? h0 : h1;
                AFL[ai] = (u == 0) ? l0 : l1;
            }
        }
        if (k0 == 0) asm volatile("cp.async.wait_group 0;" ::: "memory");
        __syncthreads();

#pragma unroll
        for (int ks = 0; ks < 2; ks++) {
            uint32_t ah[2][4], al[2][4];
#pragma unroll
            for (int mt = 0; mt < 2; mt++) {
                const uint32_t base = (((wm * 2 + mt) * 2 + ks) * 32 + pl) * 4;
                uint4 th = *(const uint4*)&AFH[base];
                uint4 tl = *(const uint4*)&AFL[base];
                ah[mt][0] = th.x; ah[mt][1] = th.y; ah[mt][2] = th.z; ah[mt][3] = th.w;
                al[mt][0] = tl.x; al[mt][1] = tl.y; al[mt][2] = tl.z; al[mt][3] = tl.w;
            }
            uint32_t bhw[16], blw[16];
            {
                const uint32_t base = kt * 2560 + ((wn * 2 + ks) * 32 + pl) * 20;
#pragma unroll
                for (int q = 0; q < 4; q++) {
                    uint4 th = *(const uint4*)&BH[base + q * 4];
                    bhw[q * 4 + 0] = th.x; bhw[q * 4 + 1] = th.y;
                    bhw[q * 4 + 2] = th.z; bhw[q * 4 + 3] = th.w;
                    uint4 tl = *(const uint4*)&BL[base + q * 4];
                    blw[q * 4 + 0] = tl.x; blw[q * 4 + 1] = tl.y;
                    blw[q * 4 + 2] = tl.z; blw[q * 4 + 3] = tl.w;
                }
            }
#pragma unroll
            for (int mt = 0; mt < 2; mt++)
#pragma unroll
                for (int nt = 0; nt < 8; nt++) {
                    const uint32_t bh2[2] = {bhw[2 * nt], bhw[2 * nt + 1]};
                    const uint32_t bl2[2] = {blw[2 * nt], blw[2 * nt + 1]};
                    mma_bf16(c[mt][nt], ah[mt], bl2);   // cross terms
                    mma_bf16(c[mt][nt], al[mt], bh2);
                    mma_bf16(c[mt][nt], ah[mt], bh2);   // main term
                }
        }
        __syncthreads();
    }

    // epilogue: bias add + store
#pragma unroll
    for (int nt = 0; nt < 8; nt++) {
        const int col = wn * 64 + nt * 8 + 2 * tig;
        const float b0 = bias[col];
        const float b1 = bias[col + 1];
#pragma unroll
        for (int mt = 0; mt < 2; mt++) {
            const int r0 = m0 + wm * 32 + mt * 16 + tp;
            const int r1 = r0 + 8;
            if (r0 < N) {
                float2 v = make_float2(c[mt][nt][0] + b0, c[mt][nt][1] + b1);
                *(float2*)(out + (long)r0 * HDIM + col) = v;
            }
            if (r1 < N) {
                float2 v = make_float2(c[mt][nt][2] + b0, c[mt][nt][3] + b1);
                *(float2*)(out + (long)r1 * HDIM + col) = v;
            }
        }
    }
}

// ---------------- edge kernel: 2 edges per warp, phase-split (R6-proven) ---
__global__ __launch_bounds__(256) void edge_kernel(
    const int* __restrict__ ei, int E,
    const float* __restrict__ K, const float* __restrict__ Q,
    const float* __restrict__ V, float* __restrict__ AGG)
{
    const int w    = (blockIdx.x * blockDim.x + threadIdx.x) >> 5;
    const int lane = threadIdx.x & 31;
    const int e0   = w * 2;
    if (e0 >= E) return;
    const int e1   = (e0 + 1 < E) ? e0 + 1 : e0;

    const int s0 = __ldg(ei + e0);
    const int s1 = __ldg(ei + e1);
    const int d0 = __ldg(ei + E + e0);
    const int d1 = __ldg(ei + E + e1);

    const float4 k0 = *(const float4*)(K + (long)d0 * HDIM + lane * 4);
    const float4 q0 = *(const float4*)(Q + (long)s0 * HDIM + lane * 4);
    const float4 v0 = *(const float4*)(V + (long)s0 * HDIM + lane * 4);
    const float4 k1 = *(const float4*)(K + (long)d1 * HDIM + lane * 4);
    const float4 q1 = *(const float4*)(Q + (long)s1 * HDIM + lane * 4);
    const float4 v1 = *(const float4*)(V + (long)s1 * HDIM + lane * 4);

    {
        const float g0 = 1.f / (1.f + __expf(-(k0.x + q0.x)));
        const float g1 = 1.f / (1.f + __expf(-(k0.y + q0.y)));
        const float g2 = 1.f / (1.f + __expf(-(k0.z + q0.z)));
        const float g3 = 1.f / (1.f + __expf(-(k0.w + q0.w)));
        float* o = AGG + (long)d0 * HDIM + lane * 4;
        asm volatile("red.global.add.v4.f32 [%0], {%1, %2, %3, %4};"
                     :: "l"(o), "f"(g0 * v0.x), "f"(g1 * v0.y),
                        "f"(g2 * v0.z), "f"(g3 * v0.w)
                     : "memory");
    }
    if (e0 + 1 < E) {
        const float g0 = 1.f / (1.f + __expf(-(k1.x + q1.x)));
        const float g1 = 1.f / (1.f + __expf(-(k1.y + q1.y)));
        const float g2 = 1.f / (1.f + __expf(-(k1.z + q1.z)));
        const float g3 = 1.f / (1.f + __expf(-(k1.w + q1.w)));
        float* o = AGG + (long)d1 * HDIM + lane * 4;
        asm volatile("red.global.add.v4.f32 [%0], {%1, %2, %3, %4};"
                     :: "l"(o), "f"(g0 * v1.x), "f"(g1 * v1.y),
                        "f"(g2 * v1.z), "f"(g3 * v1.w)
                     : "memory");
    }
}

// ---------------- pooling: widened parallelism (8 row-lanes, 2x unroll) ----
__device__ __forceinline__ int lower_bound_i(const int* a, int n, int v) {
    int lo = 0, hi = n;
    while (lo < hi) { int m = (lo + hi) >> 1; if (a[m] < v) lo = m + 1; else hi = m; }
    return lo;
}

// grid (G, 4), 256 threads: 8 row-lanes x 32 cols, 2 independent accumulators
__global__ void pool_kernel(const float* __restrict__ H,
                            const int* __restrict__ batch, int N,
                            float* __restrict__ pool)
{
    const int g    = blockIdx.x;
    const int l32  = threadIdx.x & 31;
    const int c    = blockIdx.y * 32 + l32;
    const int rloc = threadIdx.x >> 5;          // 0..7
    const int lo = lower_bound_i(batch, N, g);
    const int hi = lower_bound_i(batch, N, g + 1);

    float mx0 = -3.402823466e38f, mx1 = -3.402823466e38f;
    float sm0 = 0.f, sm1 = 0.f;
    int n = lo + rloc;
    for (; n + 8 < hi; n += 16) {               // 2 independent loads in flight
        const float x0 = H[(long)n * HDIM + c];
        const float x1 = H[(long)(n + 8) * HDIM + c];
        mx0 = fmaxf(mx0, x0); sm0 += x0;
        mx1 = fmaxf(mx1, x1); sm1 += x1;
    }
    if (n < hi) {
        const float x0 = H[(long)n * HDIM + c];
        mx0 = fmaxf(mx0, x0); sm0 += x0;
    }
    float mx = fmaxf(mx0, mx1);
    float sm = sm0 + sm1;

    __shared__ float smx[8][32], ssm[8][32];
    smx[rloc][l32] = mx;
    ssm[rloc][l32] = sm;
    __syncthreads();
    if (rloc == 0) {
        mx = smx[0][l32]; sm = ssm[0][l32];
#pragma unroll
        for (int r = 1; r < 8; r++) {
            mx = fmaxf(mx, smx[r][l32]);
            sm += ssm[r][l32];
        }
        const int cnt = hi - lo;
        pool[g * (2 * HDIM) + c]        = (cnt > 0) ? mx : 0.f;
        pool[g * (2 * HDIM) + HDIM + c] = sm / fmaxf((float)cnt, 1.f);
    }
}

// ---------------- MLP head (proven) ----------------------------------------
__global__ void mlp1_kernel(const float* __restrict__ pool,
                            const float* __restrict__ W1, const float* __restrict__ b1,
                            const float* __restrict__ g1, const float* __restrict__ be1,
                            float* __restrict__ h1)
{
    const int c = blockIdx.x;   // 0..127
    const int r = threadIdx.x;  // 0..63
    float acc = b1[c];
    const float* w = W1 + (long)c * (2 * HDIM);
    const float* f = pool + (long)r * (2 * HDIM);
#pragma unroll 8
    for (int i = 0; i < 2 * HDIM; i++) acc += f[i] * w[i];

    __shared__ float red[GNUM];
    red[r] = acc; __syncthreads();
    float m = 0.f;
    if (r == 0) { for (int i = 0; i < GNUM; i++) m += red[i]; red[0] = m / GNUM; }
    __syncthreads();
    m = red[0]; __syncthreads();
    red[r] = (acc - m) * (acc - m); __syncthreads();
    float v = 0.f;
    if (r == 0) { for (int i = 0; i < GNUM; i++) v += red[i]; red[0] = v / GNUM; }
    __syncthreads();
    v = red[0];
    const float y = g1[c] * (acc - m) * rsqrtf(v + EPSBN) + be1[c];
    h1[(long)r * HDIM + c] = fmaxf(y, 0.f);
}

__global__ void mlp2_kernel(const float* __restrict__ h1,
                            const float* __restrict__ W2, const float* __restrict__ b2,
                            const float* __restrict__ g2, const float* __restrict__ be2,
                            float* __restrict__ h2)
{
    const int c = blockIdx.x;   // 0..63
    const int r = threadIdx.x;  // 0..63
    float acc = b2[c];
    const float* w = W2 + (long)c * HDIM;
    const float* f = h1 + (long)r * HDIM;
#pragma unroll 8
    for (int i = 0; i < HDIM; i++) acc += f[i] * w[i];

    __shared__ float red[GNUM];
    red[r] = acc; __syncthreads();
    float m = 0.f;
    if (r == 0) { for (int i = 0; i < GNUM; i++) m += red[i]; red[0] = m / GNUM; }
    __syncthreads();
    m = red[0]; __syncthreads();
    red[r] = (acc - m) * (acc - m); __syncthreads();
    float v = 0.f;
    if (r == 0) { for (int i = 0; i < GNUM; i++) v += red[i]; red[0] = v / GNUM; }
    __syncthreads();
    v = red[0];
    const float y = g2[c] * (acc - m) * rsqrtf(v + EPSBN) + be2[c];
    h2[(long)r * (HDIM / 2) + c] = fmaxf(y, 0.f);
}

__global__ void mlp3_kernel(const float* __restrict__ h2,
                            const float* __restrict__ W3, const float* __restrict__ b3,
                            float* __restrict__ out)
{
    const int r = threadIdx.x;
    float acc = b3[0];
#pragma unroll
    for (int i = 0; i < HDIM / 2; i++) acc += h2[(long)r * (HDIM / 2) + i] * W3[i];
    out[r] = acc;
}

// ---------------- launch -----------------
extern "C" void kernel_launch(void* const* d_in, const int* in_sizes, int n_in,
                              void* d_out, int out_size)
{
    const float* x     = (const float*)d_in[0];
    const int*   ei    = (const int*)d_in[1];
    const int*   batch = (const int*)d_in[2];
    const int N = in_sizes[0] / HDIM;
    const int E = in_sizes[1] / 2;

    const float* l0W[4], *l0b[4], *l1W[4], *l1b[4];
    for (int i = 0; i < 4; i++) {
        l0W[i] = (const float*)d_in[3 + 2 * i];
        l0b[i] = (const float*)d_in[4 + 2 * i];
        l1W[i] = (const float*)d_in[11 + 2 * i];
        l1b[i] = (const float*)d_in[12 + 2 * i];
    }
    const float* W1  = (const float*)d_in[19];
    const float* b1  = (const float*)d_in[20];
    const float* g1  = (const float*)d_in[21];
    const float* be1 = (const float*)d_in[22];
    const float* W2  = (const float*)d_in[23];
    const float* b2  = (const float*)d_in[24];
    const float* g2  = (const float*)d_in[25];
    const float* be2 = (const float*)d_in[26];
    const float* W3  = (const float*)d_in[27];
    const float* b3  = (const float*)d_in[28];
    float* out = (float*)d_out;

    float *pK, *pQ, *pV, *pH0, *pH1, *pPool, *pM1, *pM2;
    uint32_t *pBFH, *pBFL;
    cudaGetSymbolAddress((void**)&pK,  g_K);
    cudaGetSymbolAddress((void**)&pQ,  g_Q);
    cudaGetSymbolAddress((void**)&pV,  g_V);
    cudaGetSymbolAddress((void**)&pH0, g_H0);
    cudaGetSymbolAddress((void**)&pH1, g_H1);
    cudaGetSymbolAddress((void**)&pPool, g_pool);
    cudaGetSymbolAddress((void**)&pM1, g_h1m);
    cudaGetSymbolAddress((void**)&pM2, g_h2m);
    cudaGetSymbolAddress((void**)&pBFH, g_BFHg);
    cudaGetSymbolAddress((void**)&pBFL, g_BFLg);

    const int bsmem = 2 * 4 * 2560 * 4;   // 80 KB dynamic (B frags H+L)
    cudaFuncSetAttribute(gemm_bf16x3_kernel<false>,
                         cudaFuncAttributeMaxDynamicSharedMemorySize, bsmem);
    cudaFuncSetAttribute(gemm_bf16x3_kernel<true>,
                         cudaFuncAttributeMaxDynamicSharedMemorySize, bsmem);

    const dim3 ggrid((N + 127) / 128, 4);
    const int eblocks = (E + 15) / 16;   // 8 warps/block, 2 edges per warp

    // prep: frag-ordered weight split (64 blocks: 8 sel x 8 row-slices)
    split_wfrag_kernel<<<64, 256>>>(
        l0W[0], l0W[1], l0W[2], l0W[3], l1W[0], l1W[1], l1W[2], l1W[3], pBFH, pBFL);

    // layer 0
    gemm_bf16x3_kernel<false><<<ggrid, 256, bsmem>>>(x, pBFH, pBFL,
        l0b[0], l0b[1], l0b[2], l0b[3], pK, pQ, pV, pH0, N, 0);
    edge_kernel<<<eblocks, 256>>>(ei, E, pK, pQ, pV, pH0);
    // layer 1 (relu on input), weights slots 4..7
    gemm_bf16x3_kernel<true><<<ggrid, 256, bsmem>>>(pH0, pBFH, pBFL,
        l1b[0], l1b[1], l1b[2], l1b[3], pK, pQ, pV, pH1, N, 4);
    edge_kernel<<<eblocks, 256>>>(ei, E, pK, pQ, pV, pH1);
    // pooling (widened) + head (proven)
    pool_kernel<<<dim3(GNUM, 4), 256>>>(pH1, batch, N, pPool);
    mlp1_kernel<<<HDIM, GNUM>>>(pPool, W1, b1, g1, be1, pM1);
    mlp2_kernel<<<HDIM / 2, GNUM>>>(pM1, W2, b2, g2, be2, pM2);
    mlp3_kernel<<<1, GNUM>>>(pM2, W3, b3, out);
}

// round 17
// speedup vs baseline: 1.1094x; 1.0532x over previous
#include <cuda_runtime.h>
#include <cuda_bf16.h>
#include <cstdint>

#define NNODE 50000
#define HDIM  128
#define GNUM  64
#define EPSBN 1e-5f

// ---------------- device scratch (no allocs allowed) ----------------
__device__ float g_K [NNODE * HDIM];
__device__ float g_Q [NNODE * HDIM];
__device__ float g_V [NNODE * HDIM];
__device__ float g_H0[NNODE * HDIM];
__device__ float g_H1[NNODE * HDIM];
__device__ float g_pool[GNUM * 2 * HDIM];
__device__ float g_h1m[GNUM * HDIM];
__device__ float g_h2m[GNUM * (HDIM / 2)];
// pre-split frag-ordered weights: [sel 0..7][kt 0..3][2560 u32]
__device__ uint32_t g_BFHg[8 * 4 * 2560];
__device__ uint32_t g_BFLg[8 * 4 * 2560];

// ---------------- bf16 split helpers ----------------
__device__ __forceinline__ void split2(float x, float y, uint32_t& hi, uint32_t& lo) {
    __nv_bfloat162 h = __floats2bfloat162_rn(x, y);
    float hx = __bfloat162float(h.x);
    float hy = __bfloat162float(h.y);
    __nv_bfloat162 l = __floats2bfloat162_rn(x - hx, y - hy);
    hi = *(uint32_t*)&h;
    lo = *(uint32_t*)&l;
}

__device__ __forceinline__ void mma_bf16(float c[4], const uint32_t a[4], const uint32_t b[2]) {
    asm volatile(
        "mma.sync.aligned.m16n8k16.row.col.f32.bf16.bf16.f32 "
        "{%0,%1,%2,%3}, {%4,%5,%6,%7}, {%8,%9}, {%0,%1,%2,%3};"
        : "+f"(c[0]), "+f"(c[1]), "+f"(c[2]), "+f"(c[3])
        : "r"(a[0]), "r"(a[1]), "r"(a[2]), "r"(a[3]), "r"(b[0]), "r"(b[1]));
}

// lane permutation to de-alias writer banks; readers apply identically
__device__ __forceinline__ int PERM(int l) { return l ^ ((l & 8) >> 3); }

__device__ __forceinline__ void cp_async16(uint32_t smem_addr, const void* gptr) {
    asm volatile("cp.async.ca.shared.global [%0], [%1], 16;"
                 :: "r"(smem_addr), "l"(gptr));
}

// ---------------- prep: split 8 weight matrices into frag-ordered gmem -----
__global__ void split_wfrag_kernel(
    const float* __restrict__ w0, const float* __restrict__ w1,
    const float* __restrict__ w2, const float* __restrict__ w3,
    const float* __restrict__ w4, const float* __restrict__ w5,
    const float* __restrict__ w6, const float* __restrict__ w7,
    uint32_t* __restrict__ BH, uint32_t* __restrict__ BL)
{
    const int sel   = blockIdx.x >> 3;
    const int slice = blockIdx.x & 7;        // 16-row slice
    const float* w = (sel == 0) ? w0 : (sel == 1) ? w1 : (sel == 2) ? w2 : (sel == 3) ? w3
                   : (sel == 4) ? w4 : (sel == 5) ? w5 : (sel == 6) ? w6 : w7;
    const int tid = threadIdx.x;
#pragma unroll
    for (int it = 0; it < 2; it++) {
        const int idx = tid + it * 256;      // 0..511
        const int n   = slice * 16 + (idx >> 5);   // row 0..127
        const int c4g = (idx & 31) * 4;      // global k offset 0..124
        const float4 b = *(const float4*)(w + (long)n * HDIM + c4g);
        uint32_t h0, l0, h1, l1;
        split2(b.x, b.y, h0, l0);
        split2(b.z, b.w, h1, l1);
        const int kt  = c4g >> 5;
        const int c4l = c4g & 31;
        const int bwn = n >> 6;
        const int c64 = n & 63;
        const int nt  = c64 >> 3;
        const int btp = c64 & 7;
#pragma unroll
        for (int u = 0; u < 2; u++) {
            const int kp  = (c4l >> 1) + u;
            const int ks  = kp >> 3;
            const int kp8 = kp & 7;
            const int wl  = PERM(btp * 4 + (kp8 & 3));
            const int reg = kp8 >> 2;
            const long bi = (long)(sel * 4 + kt) * 2560
                          + ((bwn * 2 + ks) * 32 + wl) * 20 + nt * 2 + reg;
            BH[bi] = (u == 0) ? h0 : h1;
            BL[bi] = (u == 0) ? l0 : l1;
        }
    }
}

// ---------------- bf16x3 GEMM (R12-proven: frag smem + pre-split B) --------
// grid = (ceil(N/128), 4 weight-select), 256 threads (8 warps).
template <bool RELU_IN>
__global__ __launch_bounds__(256) void gemm_bf16x3_kernel(
    const float* __restrict__ X,
    const uint32_t* __restrict__ BFHg, const uint32_t* __restrict__ BFLg,
    const float* __restrict__ bk, const float* __restrict__ bq,
    const float* __restrict__ bv, const float* __restrict__ bs,
    float* __restrict__ oK, float* __restrict__ oQ,
    float* __restrict__ oV, float* __restrict__ oS, int N, int wbase)
{
    const int sel = blockIdx.y;
    const float* bias = (sel == 0) ? bk : (sel == 1) ? bq : (sel == 2) ? bv : bs;
    float*       out  = (sel == 0) ? oK : (sel == 1) ? oQ : (sel == 2) ? oV : oS;
    const int m0 = blockIdx.x * 128;

    __shared__ uint32_t AFH[2048], AFL[2048];   // A frags (one k-tile)
    extern __shared__ uint32_t bdyn[];          // B frags: [kt][2560] H then L
    uint32_t* BH = bdyn;                        // 4*2560
    uint32_t* BL = bdyn + 4 * 2560;

    const int tid  = threadIdx.x;
    const int wid  = tid >> 5;
    const int lane = tid & 31;
    const int wm   = wid & 3;        // 0..3 -> 32-row slab
    const int wn   = wid >> 2;       // 0..1 -> 64-col slab
    const int tig  = lane & 3;
    const int tp   = lane >> 2;
    const int pl   = PERM(lane);

    // ---- issue all B copies up front (5120 chunks of 16 B, 20 per thread) --
    {
        const uint32_t* gBH = BFHg + (long)(wbase + sel) * 4 * 2560;
        const uint32_t* gBL = BFLg + (long)(wbase + sel) * 4 * 2560;
#pragma unroll
        for (int i = 0; i < 20; i++) {
            const int c = tid + i * 256;     // 0..5119
            if (c < 2560) {
                cp_async16((uint32_t)__cvta_generic_to_shared(&BH[c * 4]), gBH + c * 4);
            } else {
                const int c2 = c - 2560;
                cp_async16((uint32_t)__cvta_generic_to_shared(&BL[c2 * 4]), gBL + c2 * 4);
            }
        }
        asm volatile("cp.async.commit_group;" ::: "memory");
    }

    float c[2][8][4];
#pragma unroll
    for (int mt = 0; mt < 2; mt++)
#pragma unroll
        for (int nt = 0; nt < 8; nt++)
#pragma unroll
            for (int j = 0; j < 4; j++) c[mt][nt][j] = 0.f;

    for (int k0 = 0; k0 < HDIM; k0 += 32) {
        const int kt = k0 >> 5;
        // ---- load + split A tile into fragment-ordered smem ----
#pragma unroll
        for (int it = 0; it < 4; it++) {
            const int idx = tid + it * 256;       // 0..1023
            const int row = idx >> 3;
            const int c4  = (idx & 7) * 4;        // k offset in tile
            const int gm  = m0 + row;
            float4 a = make_float4(0.f, 0.f, 0.f, 0.f);
            if (gm < N) a = *(const float4*)(X + (long)gm * HDIM + k0 + c4);
            if (RELU_IN) {
                a.x = fmaxf(a.x, 0.f); a.y = fmaxf(a.y, 0.f);
                a.z = fmaxf(a.z, 0.f); a.w = fmaxf(a.w, 0.f);
            }
            uint32_t h0, l0, h1, l1;
            split2(a.x, a.y, h0, l0);
            split2(a.z, a.w, h1, l1);
            const int awm = row >> 5;
            const int amt = (row >> 4) & 1;
            const int r16 = row & 15;
            const int atp = r16 & 7;
            const int jrow = r16 >> 3;
#pragma unroll
            for (int u = 0; u < 2; u++) {
                const int kp  = (c4 >> 1) + u;
                const int ks  = kp >> 3;
                const int kp8 = kp & 7;
                const int wl  = PERM(atp * 4 + (kp8 & 3));
                const int j   = jrow + ((kp8 >> 2) << 1);
                const int ai  = (((awm * 2 + amt) * 2 + ks) * 32 + wl) * 4 + j;
                AFH[ai] = (u == 0) ? h0 : h1;
                AFL[ai] = (u == 0) ? l0 : l1;
            }
        }
        if (k0 == 0) asm volatile("cp.async.wait_group 0;" ::: "memory");
        __syncthreads();

#pragma unroll
        for (int ks = 0; ks < 2; ks++) {
            uint32_t ah[2][4], al[2][4];
#pragma unroll
            for (int mt = 0; mt < 2; mt++) {
                const uint32_t base = (((wm * 2 + mt) * 2 + ks) * 32 + pl) * 4;
                uint4 th = *(const uint4*)&AFH[base];
                uint4 tl = *(const uint4*)&AFL[base];
                ah[mt][0] = th.x; ah[mt][1] = th.y; ah[mt][2] = th.z; ah[mt][3] = th.w;
                al[mt][0] = tl.x; al[mt][1] = tl.y; al[mt][2] = tl.z; al[mt][3] = tl.w;
            }
            uint32_t bhw[16], blw[16];
            {
                const uint32_t base = kt * 2560 + ((wn * 2 + ks) * 32 + pl) * 20;
#pragma unroll
                for (int q = 0; q < 4; q++) {
                    uint4 th = *(const uint4*)&BH[base + q * 4];
                    bhw[q * 4 + 0] = th.x; bhw[q * 4 + 1] = th.y;
                    bhw[q * 4 + 2] = th.z; bhw[q * 4 + 3] = th.w;
                    uint4 tl = *(const uint4*)&BL[base + q * 4];
                    blw[q * 4 + 0] = tl.x; blw[q * 4 + 1] = tl.y;
                    blw[q * 4 + 2] = tl.z; blw[q * 4 + 3] = tl.w;
                }
            }
#pragma unroll
            for (int mt = 0; mt < 2; mt++)
#pragma unroll
                for (int nt = 0; nt < 8; nt++) {
                    const uint32_t bh2[2] = {bhw[2 * nt], bhw[2 * nt + 1]};
                    const uint32_t bl2[2] = {blw[2 * nt], blw[2 * nt + 1]};
                    mma_bf16(c[mt][nt], ah[mt], bl2);   // cross terms
                    mma_bf16(c[mt][nt], al[mt], bh2);
                    mma_bf16(c[mt][nt], ah[mt], bh2);   // main term
                }
        }
        __syncthreads();
    }

    // epilogue: bias add + store
#pragma unroll
    for (int nt = 0; nt < 8; nt++) {
        const int col = wn * 64 + nt * 8 + 2 * tig;
        const float b0 = bias[col];
        const float b1 = bias[col + 1];
#pragma unroll
        for (int mt = 0; mt < 2; mt++) {
            const int r0 = m0 + wm * 32 + mt * 16 + tp;
            const int r1 = r0 + 8;
            if (r0 < N) {
                float2 v = make_float2(c[mt][nt][0] + b0, c[mt][nt][1] + b1);
                *(float2*)(out + (long)r0 * HDIM + col) = v;
            }
            if (r1 < N) {
                float2 v = make_float2(c[mt][nt][2] + b0, c[mt][nt][3] + b1);
                *(float2*)(out + (long)r1 * HDIM + col) = v;
            }
        }
    }
}

// ---------------- edge kernel: 2 edges per warp, phase-split (R6-proven) ---
__global__ __launch_bounds__(256) void edge_kernel(
    const int* __restrict__ ei, int E,
    const float* __restrict__ K, const float* __restrict__ Q,
    const float* __restrict__ V, float* __restrict__ AGG)
{
    const int w    = (blockIdx.x * blockDim.x + threadIdx.x) >> 5;
    const int lane = threadIdx.x & 31;
    const int e0   = w * 2;
    if (e0 >= E) return;
    const int e1   = (e0 + 1 < E) ? e0 + 1 : e0;

    const int s0 = __ldg(ei + e0);
    const int s1 = __ldg(ei + e1);
    const int d0 = __ldg(ei + E + e0);
    const int d1 = __ldg(ei + E + e1);

    const float4 k0 = *(const float4*)(K + (long)d0 * HDIM + lane * 4);
    const float4 q0 = *(const float4*)(Q + (long)s0 * HDIM + lane * 4);
    const float4 v0 = *(const float4*)(V + (long)s0 * HDIM + lane * 4);
    const float4 k1 = *(const float4*)(K + (long)d1 * HDIM + lane * 4);
    const float4 q1 = *(const float4*)(Q + (long)s1 * HDIM + lane * 4);
    const float4 v1 = *(const float4*)(V + (long)s1 * HDIM + lane * 4);

    {
        const float g0 = 1.f / (1.f + __expf(-(k0.x + q0.x)));
        const float g1 = 1.f / (1.f + __expf(-(k0.y + q0.y)));
        const float g2 = 1.f / (1.f + __expf(-(k0.z + q0.z)));
        const float g3 = 1.f / (1.f + __expf(-(k0.w + q0.w)));
        float* o = AGG + (long)d0 * HDIM + lane * 4;
        asm volatile("red.global.add.v4.f32 [%0], {%1, %2, %3, %4};"
                     :: "l"(o), "f"(g0 * v0.x), "f"(g1 * v0.y),
                        "f"(g2 * v0.z), "f"(g3 * v0.w)
                     : "memory");
    }
    if (e0 + 1 < E) {
        const float g0 = 1.f / (1.f + __expf(-(k1.x + q1.x)));
        const float g1 = 1.f / (1.f + __expf(-(k1.y + q1.y)));
        const float g2 = 1.f / (1.f + __expf(-(k1.z + q1.z)));
        const float g3 = 1.f / (1.f + __expf(-(k1.w + q1.w)));
        float* o = AGG + (long)d1 * HDIM + lane * 4;
        asm volatile("red.global.add.v4.f32 [%0], {%1, %2, %3, %4};"
                     :: "l"(o), "f"(g0 * v1.x), "f"(g1 * v1.y),
                        "f"(g2 * v1.z), "f"(g3 * v1.w)
                     : "memory");
    }
}

// ---------------- pooling (R15-proven) --------------------------------------
__device__ __forceinline__ int lower_bound_i(const int* a, int n, int v) {
    int lo = 0, hi = n;
    while (lo < hi) { int m = (lo + hi) >> 1; if (a[m] < v) lo = m + 1; else hi = m; }
    return lo;
}

__global__ void pool_kernel(const float* __restrict__ H,
                            const int* __restrict__ batch, int N,
                            float* __restrict__ pool)
{
    const int g    = blockIdx.x;
    const int l32  = threadIdx.x & 31;
    const int c    = blockIdx.y * 32 + l32;
    const int rloc = threadIdx.x >> 5;          // 0..7
    const int lo = lower_bound_i(batch, N, g);
    const int hi = lower_bound_i(batch, N, g + 1);

    float mx0 = -3.402823466e38f, mx1 = -3.402823466e38f;
    float sm0 = 0.f, sm1 = 0.f;
    int n = lo + rloc;
    for (; n + 8 < hi; n += 16) {
        const float x0 = H[(long)n * HDIM + c];
        const float x1 = H[(long)(n + 8) * HDIM + c];
        mx0 = fmaxf(mx0, x0); sm0 += x0;
        mx1 = fmaxf(mx1, x1); sm1 += x1;
    }
    if (n < hi) {
        const float x0 = H[(long)n * HDIM + c];
        mx0 = fmaxf(mx0, x0); sm0 += x0;
    }
    float mx = fmaxf(mx0, mx1);
    float sm = sm0 + sm1;

    __shared__ float smx[8][32], ssm[8][32];
    smx[rloc][l32] = mx;
    ssm[rloc][l32] = sm;
    __syncthreads();
    if (rloc == 0) {
        mx = smx[0][l32]; sm = ssm[0][l32];
#pragma unroll
        for (int r = 1; r < 8; r++) {
            mx = fmaxf(mx, smx[r][l32]);
            sm += ssm[r][l32];
        }
        const int cnt = hi - lo;
        pool[g * (2 * HDIM) + c]        = (cnt > 0) ? mx : 0.f;
        pool[g * (2 * HDIM) + HDIM + c] = sm / fmaxf((float)cnt, 1.f);
    }
}

// ---------------- MLP head: coalesced warp-dot, defensive version -----------
// mlp1: block = column c (128 blocks), 256 threads (8 warps).
// Warp w computes rows w, w+8, ..., w+56 with lane-coalesced loads +
// butterfly shfl_xor reduce (all lanes hold the sum; lane 0 stores).
// BN stats: thread 0 serial over 64 smem floats (trivial cost).
__global__ __launch_bounds__(256) void mlp1_kernel(
    const float* __restrict__ pool,
    const float* __restrict__ W1, const float* __restrict__ b1,
    const float* __restrict__ g1, const float* __restrict__ be1,
    float* __restrict__ h1)
{
    const int c = blockIdx.x;   // 0..127
    __shared__ float ws[2 * HDIM];
    __shared__ float hv[GNUM];
    __shared__ float bnp[2];
    const int tid  = threadIdx.x;
    const int warp = tid >> 5;
    const int lane = tid & 31;

    ws[tid] = W1[(long)c * (2 * HDIM) + tid];   // 256 threads = 256 weights
    __syncthreads();

    const float bb = b1[c];
#pragma unroll
    for (int rr = 0; rr < 8; rr++) {
        const int r = warp + rr * 8;
        const float* f = pool + (long)r * (2 * HDIM);
        float acc = 0.f;
#pragma unroll
        for (int j = 0; j < 8; j++)
            acc += f[lane + j * 32] * ws[lane + j * 32];
#pragma unroll
        for (int o = 16; o > 0; o >>= 1)
            acc += __shfl_xor_sync(0xffffffffu, acc, o);
        if (lane == 0) hv[r] = acc + bb;
    }
    __syncthreads();

    if (tid == 0) {
        float m = 0.f;
        for (int i = 0; i < GNUM; i++) m += hv[i];
        m /= GNUM;
        float v = 0.f;
        for (int i = 0; i < GNUM; i++) { const float t = hv[i] - m; v += t * t; }
        v /= GNUM;
        bnp[0] = m;
        bnp[1] = g1[c] * rsqrtf(v + EPSBN);
    }
    __syncthreads();
    if (tid < GNUM) {
        const float y = bnp[1] * (hv[tid] - bnp[0]) + be1[c];
        h1[(long)tid * HDIM + c] = fmaxf(y, 0.f);
    }
}

// mlp2: block = column c (64 blocks), 256 threads.
__global__ __launch_bounds__(256) void mlp2_kernel(
    const float* __restrict__ h1,
    const float* __restrict__ W2, const float* __restrict__ b2,
    const float* __restrict__ g2, const float* __restrict__ be2,
    float* __restrict__ h2)
{
    const int c = blockIdx.x;   // 0..63
    __shared__ float ws[HDIM];
    __shared__ float hv[GNUM];
    __shared__ float bnp[2];
    const int tid  = threadIdx.x;
    const int warp = tid >> 5;
    const int lane = tid & 31;

    if (tid < HDIM) ws[tid] = W2[(long)c * HDIM + tid];
    __syncthreads();

    const float bb = b2[c];
#pragma unroll
    for (int rr = 0; rr < 8; rr++) {
        const int r = warp + rr * 8;
        const float* f = h1 + (long)r * HDIM;
        float acc = 0.f;
#pragma unroll
        for (int j = 0; j < 4; j++)
            acc += f[lane + j * 32] * ws[lane + j * 32];
#pragma unroll
        for (int o = 16; o > 0; o >>= 1)
            acc += __shfl_xor_sync(0xffffffffu, acc, o);
        if (lane == 0) hv[r] = acc + bb;
    }
    __syncthreads();

    if (tid == 0) {
        float m = 0.f;
        for (int i = 0; i < GNUM; i++) m += hv[i];
        m /= GNUM;
        float v = 0.f;
        for (int i = 0; i < GNUM; i++) { const float t = hv[i] - m; v += t * t; }
        v /= GNUM;
        bnp[0] = m;
        bnp[1] = g2[c] * rsqrtf(v + EPSBN);
    }
    __syncthreads();
    if (tid < GNUM) {
        const float y = bnp[1] * (hv[tid] - bnp[0]) + be2[c];
        h2[(long)tid * (HDIM / 2) + c] = fmaxf(y, 0.f);
    }
}

__global__ void mlp3_kernel(const float* __restrict__ h2,
                            const float* __restrict__ W3, const float* __restrict__ b3,
                            float* __restrict__ out)
{
    const int r = threadIdx.x;
    float acc = b3[0];
#pragma unroll
    for (int i = 0; i < HDIM / 2; i++) acc += h2[(long)r * (HDIM / 2) + i] * W3[i];
    out[r] = acc;
}

// ---------------- launch -----------------
extern "C" void kernel_launch(void* const* d_in, const int* in_sizes, int n_in,
                              void* d_out, int out_size)
{
    const float* x     = (const float*)d_in[0];
    const int*   ei    = (const int*)d_in[1];
    const int*   batch = (const int*)d_in[2];
    const int N = in_sizes[0] / HDIM;
    const int E = in_sizes[1] / 2;

    const float* l0W[4], *l0b[4], *l1W[4], *l1b[4];
    for (int i = 0; i < 4; i++) {
        l0W[i] = (const float*)d_in[3 + 2 * i];
        l0b[i] = (const float*)d_in[4 + 2 * i];
        l1W[i] = (const float*)d_in[11 + 2 * i];
        l1b[i] = (const float*)d_in[12 + 2 * i];
    }
    const float* W1  = (const float*)d_in[19];
    const float* b1  = (const float*)d_in[20];
    const float* g1  = (const float*)d_in[21];
    const float* be1 = (const float*)d_in[22];
    const float* W2  = (const float*)d_in[23];
    const float* b2  = (const float*)d_in[24];
    const float* g2  = (const float*)d_in[25];
    const float* be2 = (const float*)d_in[26];
    const float* W3  = (const float*)d_in[27];
    const float* b3  = (const float*)d_in[28];
    float* out = (float*)d_out;

    float *pK, *pQ, *pV, *pH0, *pH1, *pPool, *pM1, *pM2;
    uint32_t *pBFH, *pBFL;
    cudaGetSymbolAddress((void**)&pK,  g_K);
    cudaGetSymbolAddress((void**)&pQ,  g_Q);
    cudaGetSymbolAddress((void**)&pV,  g_V);
    cudaGetSymbolAddress((void**)&pH0, g_H0);
    cudaGetSymbolAddress((void**)&pH1, g_H1);
    cudaGetSymbolAddress((void**)&pPool, g_pool);
    cudaGetSymbolAddress((void**)&pM1, g_h1m);
    cudaGetSymbolAddress((void**)&pM2, g_h2m);
    cudaGetSymbolAddress((void**)&pBFH, g_BFHg);
    cudaGetSymbolAddress((void**)&pBFL, g_BFLg);

    const int bsmem = 2 * 4 * 2560 * 4;   // 80 KB dynamic (B frags H+L)
    cudaFuncSetAttribute(gemm_bf16x3_kernel<false>,
                         cudaFuncAttributeMaxDynamicSharedMemorySize, bsmem);
    cudaFuncSetAttribute(gemm_bf16x3_kernel<true>,
                         cudaFuncAttributeMaxDynamicSharedMemorySize, bsmem);

    const dim3 ggrid((N + 127) / 128, 4);
    const int eblocks = (E + 15) / 16;   // 8 warps/block, 2 edges per warp

    // prep: frag-ordered weight split (64 blocks: 8 sel x 8 row-slices)
    split_wfrag_kernel<<<64, 256>>>(
        l0W[0], l0W[1], l0W[2], l0W[3], l1W[0], l1W[1], l1W[2], l1W[3], pBFH, pBFL);

    // layer 0
    gemm_bf16x3_kernel<false><<<ggrid, 256, bsmem>>>(x, pBFH, pBFL,
        l0b[0], l0b[1], l0b[2], l0b[3], pK, pQ, pV, pH0, N, 0);
    edge_kernel<<<eblocks, 256>>>(ei, E, pK, pQ, pV, pH0);
    // layer 1 (relu on input), weights slots 4..7
    gemm_bf16x3_kernel<true><<<ggrid, 256, bsmem>>>(pH0, pBFH, pBFL,
        l1b[0], l1b[1], l1b[2], l1b[3], pK, pQ, pV, pH1, N, 4);
    edge_kernel<<<eblocks, 256>>>(ei, E, pK, pQ, pV, pH1);
    // pooling + head
    pool_kernel<<<dim3(GNUM, 4), 256>>>(pH1, batch, N, pPool);
    mlp1_kernel<<<HDIM, 256>>>(pPool, W1, b1, g1, be1, pM1);
    mlp2_kernel<<<HDIM / 2, 256>>>(pM1, W2, b2, g2, be2, pM2);
    mlp3_kernel<<<1, GNUM>>>(pM2, W3, b3, out);
}